// round 9
// baseline (speedup 1.0000x reference)
#include <cuda_runtime.h>
#include <math.h>
#include <stdint.h>

#define NN 5000
#define NE 100000
#define MULC 128

// ---------------- device scratch (static, no allocation) ----------------
__device__ float g_x[NN * MULC];
__device__ float g_Meff[16 * 256];
__device__ int   g_cnt[NN];
__device__ int   g_cur[NN];
__device__ int   g_off[NN + 1];
__device__ int   g_perm[NE];
__device__ float g_A[(size_t)NE * MULC * 4];
__device__ float g_gate[(size_t)NE * MULC];
__device__ float g_wm1x[(size_t)NE * MULC];
__device__ float g_mmsh3[NE * 3];
__device__ float g_dens[NE];
__device__ float g_msglin[NN * MULC * 16];
__device__ float g_mmlin[NN * MULC * 4];

__device__ __forceinline__ float silu_f(float x) { return x / (1.0f + __expf(-x)); }
__device__ __forceinline__ float2 f2(float a, float b) { return make_float2(a, b); }
__device__ __forceinline__ float2 make2(float x) { return make_float2(x, x); }
__device__ __forceinline__ float2 ffma2(float2 a, float2 b, float2 c) {
    unsigned long long ra = *reinterpret_cast<unsigned long long*>(&a);
    unsigned long long rb = *reinterpret_cast<unsigned long long*>(&b);
    unsigned long long rc = *reinterpret_cast<unsigned long long*>(&c);
    unsigned long long rd;
    asm("fma.rn.f32x2 %0, %1, %2, %3;" : "=l"(rd) : "l"(ra), "l"(rb), "l"(rc));
    return *reinterpret_cast<float2*>(&rd);
}

// ---------------- launch 1: x = nf@Wup/sqrt(128)  AND  receiver histogram ----------------
// g_cnt is zero at entry: zero-initialized at module load, then re-zeroed by
// k_scanmeff at the end of every replay (self-restoring state).
__global__ void __launch_bounds__(128) k_hx(const float* __restrict__ nf,
                                            const float* __restrict__ Wup,
                                            const int* __restrict__ ei) {
    __shared__ float s[128];
    int n = blockIdx.x, t = threadIdx.x;
    s[t] = nf[n * 128 + t];
    __syncthreads();
    float acc = 0.f;
#pragma unroll 8
    for (int u = 0; u < 128; u++) acc += s[u] * Wup[u * 128 + t];
    g_x[n * 128 + t] = acc * 0.08838834764831845f;
    int gid = n * 128 + t;
    if (gid < NE) atomicAdd(&g_cnt[ei[NE + gid]], 1);
}

// ---------------- launch 2: Meff + CSR scan + self-restore zeroing (1 block) ----------------
__global__ void __launch_bounds__(1024) k_scanmeff(
    const float* __restrict__ M1, const float* __restrict__ M2,
    const float* __restrict__ M3, const float* __restrict__ M4) {
    __shared__ float T1[16 * 64];
    __shared__ float T2[16 * 64];
    __shared__ int   s[1024];
    int t = threadIdx.x;
    // --- Meff = M1@M2@M3@M4 / 2048 (no activation -> pure linear chain) ---
    for (int idx = t; idx < 16 * 64; idx += 1024) {
        int a = idx >> 6, k = idx & 63;
        float acc = 0.f;
        for (int b = 0; b < 64; b++) acc += M1[a * 64 + b] * M2[b * 64 + k];
        T1[idx] = acc;
    }
    __syncthreads();
    for (int idx = t; idx < 16 * 64; idx += 1024) {
        int a = idx >> 6, k = idx & 63;
        float acc = 0.f;
        for (int b = 0; b < 64; b++) acc += T1[a * 64 + b] * M3[b * 64 + k];
        T2[idx] = acc;
    }
    __syncthreads();
    for (int idx = t; idx < 16 * 256; idx += 1024) {
        int a = idx >> 8, c = idx & 255;
        float acc = 0.f;
        for (int b = 0; b < 64; b++) acc += T2[a * 64 + b] * M4[b * 256 + c];
        g_Meff[idx] = acc * 4.8828125e-4f;
    }
    // --- exclusive scan of g_cnt -> g_off ---
    int carry = 0;
    for (int base = 0; base < NN; base += 1024) {
        int i = base + t;
        int c = (i < NN) ? g_cnt[i] : 0;
        s[t] = c;
        __syncthreads();
        for (int d = 1; d < 1024; d <<= 1) {
            int v = (t >= d) ? s[t - d] : 0;
            __syncthreads();
            s[t] += v;
            __syncthreads();
        }
        if (i < NN) g_off[i] = carry + s[t] - c;
        carry += s[1023];
        __syncthreads();
    }
    if (t == 0) g_off[NN] = NE;
    __syncthreads();
    // --- self-restore: zero g_cnt (next replay's hist) and g_cur (this replay's scatter) ---
    for (int i = t; i < NN; i += 1024) { g_cnt[i] = 0; g_cur[i] = 0; }
}

// ---------------- launch 3: scatter edges into CSR order ----------------
__global__ void __launch_bounds__(256) k_scatter(const int* __restrict__ ei) {
    int e = blockIdx.x * blockDim.x + threadIdx.x;
    if (e < NE) {
        int r = ei[NE + e];
        int k = atomicAdd(&g_cur[r], 1);
        g_perm[g_off[r] + k] = e;
    }
}

// ---------------- launch 4: edge kernel (R6 FFMA2 version, proven correct) ----------------
__global__ void __launch_bounds__(256) k_edge(
    const float* __restrict__ W1, const float* __restrict__ W2,
    const float* __restrict__ W3, const float* __restrict__ W4,
    const float* __restrict__ ea, const float* __restrict__ ef,
    const float* __restrict__ mmi, const float* __restrict__ mma,
    const float* __restrict__ Wd, const int* __restrict__ ei)
{
    __shared__ float s_efT[16][8];
    __shared__ float s_h1[8][64];
    __shared__ float s_h2[8 * 65];
    __shared__ float s_h3T[64][8];
    __shared__ float s_w4[8][512];
    __shared__ float s_wmm[8][256];
    __shared__ int   s_e[8], s_send[8];
    __shared__ float s_sh0[8], s_mm0[8];

    int t = threadIdx.x;
    int p0 = blockIdx.x * 8;

    if (t < 8) {
        int e = g_perm[p0 + t];
        s_e[t] = e;
        s_send[t] = ei[e];
    }
    __syncthreads();
    if (t < 128) {
        int el = t >> 4, j = t & 15;
        int e = s_e[el], sd = s_send[el];
        s_efT[j][el] = (j < 8) ? ef[e * 8 + j] : mmi[sd * 8 + (j - 8)];
    }
    __syncthreads();
    for (int r = 0; r < 2; r++) {
        int oi = t + 256 * r, el = oi >> 6, i = oi & 63;
        float s = 0.f;
#pragma unroll
        for (int j = 0; j < 16; j++) s += s_efT[j][el] * W1[j * 64 + i];
        s_h1[el][i] = silu_f(s * 0.25f);
    }
    __syncthreads();
    for (int r = 0; r < 2; r++) {
        int oi = t + 256 * r, el = oi >> 6, i = oi & 63;
        float s = 0.f;
#pragma unroll 8
        for (int j = 0; j < 64; j++) s += s_h1[el][j] * W2[j * 64 + i];
        s_h2[el * 65 + i] = silu_f(s * 0.125f);
    }
    __syncthreads();
    for (int r = 0; r < 2; r++) {
        int oi = t + 256 * r, el = oi & 7, i = oi >> 3;
        float s = 0.f;
#pragma unroll 8
        for (int j = 0; j < 64; j++) s += s_h2[el * 65 + j] * W3[j * 64 + i];
        s_h3T[i][el] = silu_f(s * 0.125f);
    }
    __syncthreads();
    {
        float2 a0[4], a1[4];
#pragma unroll
        for (int p = 0; p < 4; p++) { a0[p] = make_float2(0.f, 0.f); a1[p] = make_float2(0.f, 0.f); }
#pragma unroll 4
        for (int j = 0; j < 64; j++) {
            float2 w = *(const float2*)&W4[j * 512 + 2 * t];
            float4 h0 = *(const float4*)&s_h3T[j][0];
            float4 h1 = *(const float4*)&s_h3T[j][4];
            float2 hp0 = f2(h0.x, h0.y), hp1 = f2(h0.z, h0.w);
            float2 hp2 = f2(h1.x, h1.y), hp3 = f2(h1.z, h1.w);
            float2 w0 = make2(w.x), w1 = make2(w.y);
            a0[0] = ffma2(hp0, w0, a0[0]); a1[0] = ffma2(hp0, w1, a1[0]);
            a0[1] = ffma2(hp1, w0, a0[1]); a1[1] = ffma2(hp1, w1, a1[1]);
            a0[2] = ffma2(hp2, w0, a0[2]); a1[2] = ffma2(hp2, w1, a1[2]);
            a0[3] = ffma2(hp3, w0, a0[3]); a1[3] = ffma2(hp3, w1, a1[3]);
        }
#pragma unroll
        for (int p = 0; p < 4; p++) {
            s_w4[2 * p][2 * t]         = a0[p].x * 0.125f;
            s_w4[2 * p + 1][2 * t]     = a0[p].y * 0.125f;
            s_w4[2 * p][2 * t + 1]     = a1[p].x * 0.125f;
            s_w4[2 * p + 1][2 * t + 1] = a1[p].y * 0.125f;
        }
    }
    {
        float2 ac[4];
#pragma unroll
        for (int p = 0; p < 4; p++) ac[p] = make_float2(0.f, 0.f);
#pragma unroll
        for (int j = 0; j < 16; j++) {
            float2 m = make2(g_Meff[j * 256 + t]);
            float4 e0 = *(const float4*)&s_efT[j][0];
            float4 e1 = *(const float4*)&s_efT[j][4];
            ac[0] = ffma2(f2(e0.x, e0.y), m, ac[0]);
            ac[1] = ffma2(f2(e0.z, e0.w), m, ac[1]);
            ac[2] = ffma2(f2(e1.x, e1.y), m, ac[2]);
            ac[3] = ffma2(f2(e1.z, e1.w), m, ac[3]);
        }
#pragma unroll
        for (int p = 0; p < 4; p++) {
            s_wmm[2 * p][t]     = ac[p].x;
            s_wmm[2 * p + 1][t] = ac[p].y;
        }
    }
    if (t < 8) {
        int el = t;
        int e = s_e[el], sd = s_send[el];
        s_sh0[el] = ea[(size_t)e * 16];
        float q = 0.f;
#pragma unroll
        for (int j = 0; j < 8; j++) q += ef[e * 8 + j] * Wd[j];
        q *= 0.35355339059327373f;
        g_dens[p0 + el] = tanhf(q * q);
        s_mm0[el] = mma[sd * 4];
        g_mmsh3[(p0 + el) * 3 + 0] = mma[sd * 4 + 1];
        g_mmsh3[(p0 + el) * 3 + 1] = mma[sd * 4 + 2];
        g_mmsh3[(p0 + el) * 3 + 2] = mma[sd * 4 + 3];
    }
    __syncthreads();
#pragma unroll
    for (int r = 0; r < 4; r++) {
        int pair = t + 256 * r;
        int el = pair >> 7, u = pair & 127;
        int p = p0 + el;
        float xj = g_x[s_send[el] * 128 + u];
        float4 w4 = *(const float4*)&s_w4[el][u * 4];
        float pre = w4.x * xj * s_sh0[el];
        float wm0 = s_wmm[el][u * 2 + 0] * pre;
        float wm1 = s_wmm[el][u * 2 + 1] * pre;
        float gate = wm0 * xj * s_mm0[el];
        size_t b = (size_t)p * 128 + u;
        g_gate[b] = gate;
        g_wm1x[b] = wm1 * xj;
        float gx = gate * xj;
        float4 A;
        A.x = w4.x * gx; A.y = w4.y * gx; A.z = w4.z * gx; A.w = w4.w * gx;
        reinterpret_cast<float4*>(g_A)[b] = A;
    }
}

// ---------------- launch 5: aggregation + per-l linear, node-pair FFMA2 phase-2 ----------------
__global__ void __launch_bounds__(128) k_agg(const float* __restrict__ ea,
                                             const float* __restrict__ Wlin,
                                             const float* __restrict__ Wmlin)
{
    // tn-pair interleaved staging: s_msgP[P][uu*18 + m] = (acc_tn(2P), acc_tn(2P+1))
    __shared__ float2 s_msgP[2][128 * 18];   // 36864 B
    __shared__ float2 s_mmP[2][128 * 5];     // 10240 B
    __shared__ float  s_d[4];
    int u = threadIdx.x;
    int n0 = blockIdx.x * 4;

    for (int tn = 0; tn < 4; tn++) {
        int n = n0 + tn;
        float acc[16], am[4];
#pragma unroll
        for (int m = 0; m < 16; m++) acc[m] = 0.f;
#pragma unroll
        for (int j = 0; j < 4; j++) am[j] = 0.f;
        float dl = 0.f;
        int pb = g_off[n], pe = g_off[n + 1];
        for (int p = pb; p < pe; p++) {
            int e = g_perm[p];
            size_t b = (size_t)p * 128 + u;
            float4 A = reinterpret_cast<const float4*>(g_A)[b];
            float gate = g_gate[b];
            float wx = g_wm1x[b];
            const float* sh = ea + (size_t)e * 16;
            acc[0] += A.x * __ldg(sh + 0);
            acc[1] += A.y * __ldg(sh + 1);
            acc[2] += A.y * __ldg(sh + 2);
            acc[3] += A.y * __ldg(sh + 3);
#pragma unroll
            for (int m = 4; m < 9; m++) acc[m] += A.z * __ldg(sh + m);
#pragma unroll
            for (int m = 9; m < 16; m++) acc[m] += A.w * __ldg(sh + m);
            am[0] += gate;
            am[1] += wx * __ldg(&g_mmsh3[p * 3 + 0]);
            am[2] += wx * __ldg(&g_mmsh3[p * 3 + 1]);
            am[3] += wx * __ldg(&g_mmsh3[p * 3 + 2]);
            dl += __ldg(&g_dens[p]);
        }
        int P = tn >> 1, h = tn & 1;
        float* mb = reinterpret_cast<float*>(&s_msgP[P][u * 18]);
#pragma unroll
        for (int m = 0; m < 16; m++) mb[2 * m + h] = acc[m];
        float* qb = reinterpret_cast<float*>(&s_mmP[P][u * 5]);
#pragma unroll
        for (int j = 0; j < 4; j++) qb[2 * j + h] = am[j];
        if (u == 0) s_d[tn] = dl;
    }
    __syncthreads();

    int v = u;
    float2 linP[2][16];
    float2 lmmP[2][4];
#pragma unroll
    for (int P = 0; P < 2; P++) {
#pragma unroll
        for (int m = 0; m < 16; m++) linP[P][m] = make_float2(0.f, 0.f);
#pragma unroll
        for (int j = 0; j < 4; j++) lmmP[P][j] = make_float2(0.f, 0.f);
    }
    for (int uu = 0; uu < 128; uu++) {
        float2 w0 = make2(Wlin[(0 * 128 + uu) * 128 + v]);
        float2 w1 = make2(Wlin[(1 * 128 + uu) * 128 + v]);
        float2 w2 = make2(Wlin[(2 * 128 + uu) * 128 + v]);
        float2 w3 = make2(Wlin[(3 * 128 + uu) * 128 + v]);
        float2 m0 = make2(Wmlin[(0 * 128 + uu) * 128 + v]);
        float2 m1 = make2(Wmlin[(1 * 128 + uu) * 128 + v]);
#pragma unroll
        for (int P = 0; P < 2; P++) {
            const float4* Q = reinterpret_cast<const float4*>(&s_msgP[P][uu * 18]);
            float4 c0 = Q[0], c1 = Q[1], c2 = Q[2], c3 = Q[3];
            float4 c4 = Q[4], c5 = Q[5], c6 = Q[6], c7 = Q[7];
            linP[P][0]  = ffma2(f2(c0.x, c0.y), w0, linP[P][0]);
            linP[P][1]  = ffma2(f2(c0.z, c0.w), w1, linP[P][1]);
            linP[P][2]  = ffma2(f2(c1.x, c1.y), w1, linP[P][2]);
            linP[P][3]  = ffma2(f2(c1.z, c1.w), w1, linP[P][3]);
            linP[P][4]  = ffma2(f2(c2.x, c2.y), w2, linP[P][4]);
            linP[P][5]  = ffma2(f2(c2.z, c2.w), w2, linP[P][5]);
            linP[P][6]  = ffma2(f2(c3.x, c3.y), w2, linP[P][6]);
            linP[P][7]  = ffma2(f2(c3.z, c3.w), w2, linP[P][7]);
            linP[P][8]  = ffma2(f2(c4.x, c4.y), w2, linP[P][8]);
            linP[P][9]  = ffma2(f2(c4.z, c4.w), w3, linP[P][9]);
            linP[P][10] = ffma2(f2(c5.x, c5.y), w3, linP[P][10]);
            linP[P][11] = ffma2(f2(c5.z, c5.w), w3, linP[P][11]);
            linP[P][12] = ffma2(f2(c6.x, c6.y), w3, linP[P][12]);
            linP[P][13] = ffma2(f2(c6.z, c6.w), w3, linP[P][13]);
            linP[P][14] = ffma2(f2(c7.x, c7.y), w3, linP[P][14]);
            linP[P][15] = ffma2(f2(c7.z, c7.w), w3, linP[P][15]);
            const float2* M = &s_mmP[P][uu * 5];
            lmmP[P][0] = ffma2(M[0], m0, lmmP[P][0]);
            lmmP[P][1] = ffma2(M[1], m1, lmmP[P][1]);
            lmmP[P][2] = ffma2(M[2], m1, lmmP[P][2]);
            lmmP[P][3] = ffma2(M[3], m1, lmmP[P][3]);
        }
    }
    const float sL = 0.08838834764831845f;
#pragma unroll
    for (int tn = 0; tn < 4; tn++) {
        int P = tn >> 1, h = tn & 1;
        float inv = sL / (s_d[tn] + 1.0f);
        size_t ob = ((size_t)(n0 + tn) * 128 + v) * 16;
#pragma unroll
        for (int m = 0; m < 16; m++)
            g_msglin[ob + m] = (h ? linP[P][m].y : linP[P][m].x) * inv;
        float im = sL * 0.05f;
        size_t ob2 = ((size_t)(n0 + tn) * 128 + v) * 4;
#pragma unroll
        for (int j = 0; j < 4; j++)
            g_mmlin[ob2 + j] = (h ? lmmP[P][j].y : lmmP[P][j].x) * im;
    }
}

// ---------------- launch 6: skip TP, node-pair FFMA2, same memory behavior as R2 ----------------
__global__ void __launch_bounds__(128) k_skip(const float* __restrict__ na,
                                              const float* __restrict__ Wsk,
                                              const float* __restrict__ Wmsk,
                                              float* __restrict__ out)
{
    __shared__ float2 s_ml[2][128 * 18];   // 36864 B : [P][uu*18+m] = (msg_tn2P, msg_tn2P+1)
    __shared__ float2 s_mm[2][128 * 5];    // 10240 B
    int v = threadIdx.x;
    int n0 = blockIdx.x * 4;

#pragma unroll
    for (int P = 0; P < 2; P++) {
        const float* a0 = &g_msglin[(size_t)(n0 + 2 * P) * 2048];
        const float* a1 = &g_msglin[(size_t)(n0 + 2 * P + 1) * 2048];
        for (int idx = v; idx < 2048; idx += 128) {
            int uu = idx >> 4, m = idx & 15;
            s_ml[P][uu * 18 + m] = f2(__ldg(a0 + idx), __ldg(a1 + idx));
        }
        const float* b0 = &g_mmlin[(size_t)(n0 + 2 * P) * 512];
        const float* b1 = &g_mmlin[(size_t)(n0 + 2 * P + 1) * 512];
        for (int idx = v; idx < 512; idx += 128) {
            int uu = idx >> 2, j = idx & 3;
            s_mm[P][uu * 5 + j] = f2(__ldg(b0 + idx), __ldg(b1 + idx));
        }
    }
    float2 atp[2][10];
#pragma unroll
    for (int P = 0; P < 2; P++)
#pragma unroll
        for (int z = 0; z < 10; z++)
            atp[P][z] = f2(__ldg(&na[(n0 + 2 * P) * 10 + z]),
                           __ldg(&na[(n0 + 2 * P + 1) * 10 + z]));
    __syncthreads();

    float2 a1[2][16], a2[2][4];
#pragma unroll
    for (int P = 0; P < 2; P++) {
#pragma unroll
        for (int m = 0; m < 16; m++) a1[P][m] = make_float2(0.f, 0.f);
#pragma unroll
        for (int j = 0; j < 4; j++) a2[P][j] = make_float2(0.f, 0.f);
    }

    for (int uu = 0; uu < 128; uu++) {
        float2 ttp[2][4];
#pragma unroll
        for (int l = 0; l < 4; l++) { ttp[0][l] = make_float2(0.f, 0.f); ttp[1][l] = make_float2(0.f, 0.f); }
#pragma unroll
        for (int l = 0; l < 4; l++) {
#pragma unroll
            for (int z = 0; z < 10; z++) {
                float2 wp = make2(__ldg(&Wsk[(((size_t)l * 128 + uu) * 10 + z) * 128 + v]));
                ttp[0][l] = ffma2(atp[0][z], wp, ttp[0][l]);
                ttp[1][l] = ffma2(atp[1][z], wp, ttp[1][l]);
            }
        }
#pragma unroll
        for (int P = 0; P < 2; P++) {
            const float4* Q = reinterpret_cast<const float4*>(&s_ml[P][uu * 18]);
            float4 c0 = Q[0], c1 = Q[1], c2 = Q[2], c3 = Q[3];
            float4 c4 = Q[4], c5 = Q[5], c6 = Q[6], c7 = Q[7];
            a1[P][0]  = ffma2(f2(c0.x, c0.y), ttp[P][0], a1[P][0]);
            a1[P][1]  = ffma2(f2(c0.z, c0.w), ttp[P][1], a1[P][1]);
            a1[P][2]  = ffma2(f2(c1.x, c1.y), ttp[P][1], a1[P][2]);
            a1[P][3]  = ffma2(f2(c1.z, c1.w), ttp[P][1], a1[P][3]);
            a1[P][4]  = ffma2(f2(c2.x, c2.y), ttp[P][2], a1[P][4]);
            a1[P][5]  = ffma2(f2(c2.z, c2.w), ttp[P][2], a1[P][5]);
            a1[P][6]  = ffma2(f2(c3.x, c3.y), ttp[P][2], a1[P][6]);
            a1[P][7]  = ffma2(f2(c3.z, c3.w), ttp[P][2], a1[P][7]);
            a1[P][8]  = ffma2(f2(c4.x, c4.y), ttp[P][2], a1[P][8]);
            a1[P][9]  = ffma2(f2(c4.z, c4.w), ttp[P][3], a1[P][9]);
            a1[P][10] = ffma2(f2(c5.x, c5.y), ttp[P][3], a1[P][10]);
            a1[P][11] = ffma2(f2(c5.z, c5.w), ttp[P][3], a1[P][11]);
            a1[P][12] = ffma2(f2(c6.x, c6.y), ttp[P][3], a1[P][12]);
            a1[P][13] = ffma2(f2(c6.z, c6.w), ttp[P][3], a1[P][13]);
            a1[P][14] = ffma2(f2(c7.x, c7.y), ttp[P][3], a1[P][14]);
            a1[P][15] = ffma2(f2(c7.z, c7.w), ttp[P][3], a1[P][15]);
        }
        float2 t2p[2][2];
        t2p[0][0] = make_float2(0.f, 0.f); t2p[0][1] = make_float2(0.f, 0.f);
        t2p[1][0] = make_float2(0.f, 0.f); t2p[1][1] = make_float2(0.f, 0.f);
#pragma unroll
        for (int l = 0; l < 2; l++) {
#pragma unroll
            for (int z = 0; z < 10; z++) {
                float2 wp = make2(__ldg(&Wmsk[(((size_t)l * 128 + uu) * 10 + z) * 128 + v]));
                t2p[0][l] = ffma2(atp[0][z], wp, t2p[0][l]);
                t2p[1][l] = ffma2(atp[1][z], wp, t2p[1][l]);
            }
        }
#pragma unroll
        for (int P = 0; P < 2; P++) {
            const float2* M = &s_mm[P][uu * 5];
            a2[P][0] = ffma2(M[0], t2p[P][0], a2[P][0]);
            a2[P][1] = ffma2(M[1], t2p[P][1], a2[P][1]);
            a2[P][2] = ffma2(M[2], t2p[P][1], a2[P][2]);
            a2[P][3] = ffma2(M[3], t2p[P][1], a2[P][3]);
        }
    }
    const float sc = 0.02795084971874737f;  // 1/sqrt(1280)
#pragma unroll
    for (int P = 0; P < 2; P++) {
#pragma unroll
        for (int h = 0; h < 2; h++) {
            int n = n0 + 2 * P + h;
            size_t ob = ((size_t)n * 128 + v) * 16;
#pragma unroll
            for (int m = 0; m < 16; m++)
                out[ob + m] = (h ? a1[P][m].y : a1[P][m].x) * sc;
            size_t ob2 = (size_t)NN * 2048 + ob;
#pragma unroll
            for (int m = 0; m < 4; m++)
                out[ob2 + m] = (h ? a2[P][m].y : a2[P][m].x) * sc;
#pragma unroll
            for (int m = 4; m < 16; m++) out[ob2 + m] = 0.f;  // mm l=2,3 have no path
        }
    }
}

// ---------------- host ----------------
extern "C" void kernel_launch(void* const* d_in, const int* in_sizes, int n_in,
                              void* d_out, int out_size)
{
    const int* ei;
    int wi;
    if (in_sizes[6] == 2 * NE) { ei = (const int*)d_in[6]; wi = 7; }
    else                       { ei = (const int*)d_in[n_in - 1]; wi = 6; }

    const float* na   = (const float*)d_in[0];
    const float* nf   = (const float*)d_in[1];
    const float* ea   = (const float*)d_in[2];
    const float* ef   = (const float*)d_in[3];
    const float* mmi  = (const float*)d_in[4];
    const float* mma  = (const float*)d_in[5];
    const float* Wup  = (const float*)d_in[wi + 0];
    const float* W1   = (const float*)d_in[wi + 1];
    const float* W2   = (const float*)d_in[wi + 2];
    const float* W3   = (const float*)d_in[wi + 3];
    const float* W4   = (const float*)d_in[wi + 4];
    const float* M1   = (const float*)d_in[wi + 5];
    const float* M2   = (const float*)d_in[wi + 6];
    const float* M3   = (const float*)d_in[wi + 7];
    const float* M4   = (const float*)d_in[wi + 8];
    const float* Wd   = (const float*)d_in[wi + 9];
    const float* Wlin = (const float*)d_in[wi + 10];
    const float* Wmlin= (const float*)d_in[wi + 11];
    const float* Wsk  = (const float*)d_in[wi + 12];
    const float* Wmsk = (const float*)d_in[wi + 13];
    float* out = (float*)d_out;

    k_hx<<<NN, 128>>>(nf, Wup, ei);                 // launch 1: x + hist
    k_scanmeff<<<1, 1024>>>(M1, M2, M3, M4);        // launch 2: Meff + scan + self-restore zero
    k_scatter<<<(NE + 255) / 256, 256>>>(ei);       // launch 3
    k_edge<<<NE / 8, 256>>>(W1, W2, W3, W4, ea, ef, mmi, mma, Wd, ei);  // launch 4
    k_agg<<<NN / 4, 128>>>(ea, Wlin, Wmlin);        // launch 5
    k_skip<<<NN / 4, 128>>>(na, Wsk, Wmsk, out);    // launch 6
}